// round 8
// baseline (speedup 1.0000x reference)
#include <cuda_runtime.h>

#define NB 32
#define NN 100000
#define NE 1000000
#define NH 64
#define NL 3
#define NRELP 231
#define NTA 365
#define NENT 7128
#define FULLM 0xffffffffu
#define CH 1024
#define NCHUNK 98   // ceil(NN/CH)

typedef unsigned long long ull;

// ---------------- device scratch ----------------
static __device__ float g_next[NN * NH];          // 25.6 MB (pre-relu aggregate)
static __device__ float g_hW[3 * NN * NH];        // 76.8 MB transformed hidden per class
static __device__ float g_RW[3 * NRELP * NH];     // rela @ W_cls^T
static __device__ float g_TW[3 * NTA * NH];       // time @ W_cls^T
static __device__ int4  g_eMeta[NE];              // sorted by src: {src|cls<<20, dst, rel|ta<<9, sci}
static __device__ float g_score[NE];
static __device__ float g_hv[NN * 8];
static __device__ float g_rq[NB * NRELP * 8];
static __device__ int   g_hist[NN];
static __device__ int   g_off[NN];
static __device__ int   g_part[NCHUNK];
static __device__ int   g_partoff[NCHUNK];

#define FMA2(d, a, b, c) \
    asm("fma.rn.f32x2 %0, %1, %2, %3;" : "=l"(d) : "l"(a), "l"(b), "l"(c))

__device__ __forceinline__ ull dup_f(float x) {
    ull r; unsigned u = __float_as_uint(x);
    asm("mov.b64 %0, {%1, %1};" : "=l"(r) : "r"(u));
    return r;
}
__device__ __forceinline__ void red4(float* p, float x, float y, float z, float w) {
    asm volatile("red.global.add.v4.f32 [%0], {%1, %2, %3, %4};"
                 :: "l"(p), "f"(x), "f"(y), "f"(z), "f"(w) : "memory");
}

// ---------------- fused init: g_next, g_hist, out ----------------
__global__ void init_kernel(float* out, int n_out) {
    int i = blockIdx.x * blockDim.x + threadIdx.x;
    int stride = gridDim.x * blockDim.x;
    const int n4 = NN * NH / 4;
    for (int j = i; j < n4; j += stride)
        ((float4*)g_next)[j] = make_float4(0.f, 0.f, 0.f, 0.f);
    for (int j = i; j < NN; j += stride) g_hist[j] = 0;
    for (int j = i; j < n_out; j += stride) out[j] = 0.f;
}

// ---------------- counting sort by src ----------------
__global__ void hist_kernel(const int* __restrict__ src_idx) {
    int e = blockIdx.x * blockDim.x + threadIdx.x;
    if (e < NE) atomicAdd(&g_hist[src_idx[e]], 1);
}
__global__ void sum_chunk_kernel() {
    __shared__ int sd[256];
    int b = blockIdx.x, t = threadIdx.x;
    int s = 0;
    for (int i = t; i < CH; i += 256) {
        int g = b * CH + i;
        if (g < NN) s += g_hist[g];
    }
    sd[t] = s; __syncthreads();
    for (int o = 128; o; o >>= 1) { if (t < o) sd[t] += sd[t + o]; __syncthreads(); }
    if (t == 0) g_part[b] = sd[0];
}
__global__ void scan_part_kernel() {
    if (threadIdx.x == 0) {
        int run = 0;
        for (int i = 0; i < NCHUNK; ++i) { g_partoff[i] = run; run += g_part[i]; }
    }
}
__global__ void off_kernel() {
    __shared__ int sd[256];
    int b = blockIdx.x, t = threadIdx.x;
    int idx = b * CH + t * 4;
    int h0 = (idx + 0 < NN) ? g_hist[idx + 0] : 0;
    int h1 = (idx + 1 < NN) ? g_hist[idx + 1] : 0;
    int h2 = (idx + 2 < NN) ? g_hist[idx + 2] : 0;
    int h3 = (idx + 3 < NN) ? g_hist[idx + 3] : 0;
    int sum = h0 + h1 + h2 + h3;
    sd[t] = sum; __syncthreads();
    for (int o = 1; o < 256; o <<= 1) {
        int v = (t >= o) ? sd[t - o] : 0;
        __syncthreads();
        sd[t] += v;
        __syncthreads();
    }
    int base = g_partoff[b] + sd[t] - sum;
    if (idx + 0 < NN) g_off[idx + 0] = base;
    if (idx + 1 < NN) g_off[idx + 1] = base + h0;
    if (idx + 2 < NN) g_off[idx + 2] = base + h0 + h1;
    if (idx + 3 < NN) g_off[idx + 3] = base + h0 + h1 + h2;
}
__global__ void scatter_sort_kernel(const int* __restrict__ src_idx,
                                    const int* __restrict__ dst_idx,
                                    const int* __restrict__ rel_idx,
                                    const int* __restrict__ rel_time,
                                    const int* __restrict__ batch_idx) {
    int e = blockIdx.x * blockDim.x + threadIdx.x;
    if (e >= NE) return;
    int src = src_idx[e];
    int rt  = rel_time[e];
    int cls = rt > 0 ? 2 : (rt == 0 ? 1 : 0);  // 0=past(Wp) 1=now(Wn) 2=future(Wf)
    int ta  = rt < 0 ? -rt : rt;
    int rel = rel_idx[e];
    int pos = atomicAdd(&g_off[src], 1);
    g_eMeta[pos] = make_int4(src | (cls << 20), dst_idx[e],
                             rel | (ta << 9), batch_idx[e] * NRELP + rel);
}

// ---------------- per-layer tables ----------------
// RW[cls][r][h] = sum_k rela[r][k] * W_cls[h][k];  TW[cls][ta][h] likewise for time.
__global__ void rwtw_kernel(const float* __restrict__ relaL,
                            const float* __restrict__ timeE,
                            const float* __restrict__ Wp,
                            const float* __restrict__ Wn,
                            const float* __restrict__ Wf) {
    int w = (blockIdx.x * blockDim.x + threadIdx.x) >> 5;
    int lane = threadIdx.x & 31;
    const int NROW = 3 * NRELP + 3 * NTA;   // 1788
    if (w >= NROW) return;
    const float* in; float* out; int cls;
    if (w < 3 * NRELP) {
        cls = w / NRELP;
        in = relaL + (w % NRELP) * NH;
        out = g_RW + w * NH;
    } else {
        int w2 = w - 3 * NRELP;
        cls = w2 / NTA;
        in = timeE + (w2 % NTA) * NH;
        out = g_TW + w2 * NH;
    }
    const float* W = (cls == 0) ? Wp : ((cls == 1) ? Wn : Wf);
    float2 ev = __ldg((const float2*)&in[2 * lane]);
    int h0 = 2 * lane;
    float a0 = 0.f, a1 = 0.f;
#pragma unroll 8
    for (int k2 = 0; k2 < 32; ++k2) {
        float bx = __shfl_sync(FULLM, ev.x, k2);
        float by = __shfl_sync(FULLM, ev.y, k2);
        float2 w0 = __ldg((const float2*)&W[h0 * 64 + 2 * k2]);
        float2 w1 = __ldg((const float2*)&W[(h0 + 1) * 64 + 2 * k2]);
        a0 += bx * w0.x + by * w0.y;
        a1 += bx * w1.x + by * w1.y;
    }
    out[h0] = a0; out[h0 + 1] = a1;
}

// rq[b*231+r][a] = rela[r].W1seg1_a + rela[qr_b].W1seg2_a
__global__ void rq_kernel(const float* __restrict__ relaL,
                          const float* __restrict__ W1L,
                          const int* __restrict__ query_rel) {
    int w = (blockIdx.x * blockDim.x + threadIdx.x) >> 5;
    int lane = threadIdx.x & 31;
    if (w >= NB * NRELP) return;
    int b = w / NRELP, r = w % NRELP;
    int qrb = __ldg(&query_rel[b]);
    float2 re = __ldg((const float2*)&relaL[r * 64 + 2 * lane]);
    float2 qe = __ldg((const float2*)&relaL[qrb * 64 + 2 * lane]);
    float p[5];
#pragma unroll
    for (int a = 0; a < 5; ++a) {
        float2 v  = __ldg((const float2*)&W1L[a * 192 + 64 + 2 * lane]);
        float2 ww = __ldg((const float2*)&W1L[a * 192 + 128 + 2 * lane]);
        p[a] = re.x * v.x + re.y * v.y + qe.x * ww.x + qe.y * ww.y;
    }
#pragma unroll
    for (int a = 0; a < 5; ++a)
#pragma unroll
        for (int off = 16; off; off >>= 1) p[a] += __shfl_xor_sync(FULLM, p[a], off);
    if (lane == 0) {
#pragma unroll
        for (int a = 0; a < 5; ++a) g_rq[w * 8 + a] = p[a];
    }
}

// ---------------- post-layer fused kernel ----------------
// hidden = relu(g_next); g_next = 0; hv = hidden.W1seg0 (next layer); hW[cls] = hidden @ W_cls^T
__global__ void __launch_bounds__(256, 2) post_kernel(const float* __restrict__ Wp,
                                                      const float* __restrict__ Wn,
                                                      const float* __restrict__ Wf,
                                                      const float* __restrict__ W1L) {
    extern __shared__ float dyn[];
    float* sW = dyn;                 // 3*4352 floats
    float* sT = dyn + 3 * 4352;      // 128*66 floats
    float* sU = dyn + 3 * 4352 + 128 * 66;  // 5*64 floats (W1 seg0, next layer)
    int t = threadIdx.x;

    for (int idx = t; idx < 3 * 4096; idx += 256) {
        int c = idx >> 12, rem = idx & 4095;
        int h = rem >> 6, k = rem & 63;
        const float* W = (c == 0) ? Wp : ((c == 1) ? Wn : Wf);
        sW[c * 4352 + k * 68 + h + (h >= 32 ? 4 : 0)] = __ldg(&W[h * 64 + k]);
    }
    for (int idx = t; idx < 5 * 64; idx += 256) {
        int a = idx >> 6, k = idx & 63;
        sU[idx] = __ldg(&W1L[a * 192 + k]);
    }

    int tile = blockIdx.x * 128;
    int nN = min(128, NN - tile);

    // load tile with relu; zero g_next
    for (int j = t; j < nN * 32; j += 256) {
        int nl = j >> 5, l = j & 31;
        float2* gp = (float2*)(g_next + (size_t)(tile + nl) * 64 + 2 * l);
        float2 v = *gp;
        v.x = fmaxf(v.x, 0.f); v.y = fmaxf(v.y, 0.f);
        *(float2*)&sT[nl * 66 + 2 * l] = v;
        *gp = make_float2(0.f, 0.f);
    }
    __syncthreads();

    int slot = t >> 1, p = t & 1;

    // hv: pair-threads, each computes half-dot then combines via shfl
    if (slot < nN) {
        const float* row = sT + slot * 66 + p * 32;
        float pa[5] = {0.f, 0.f, 0.f, 0.f, 0.f};
#pragma unroll 8
        for (int k = 0; k < 32; ++k) {
            float hk = row[k];
#pragma unroll
            for (int a = 0; a < 5; ++a) pa[a] += hk * sU[a * 64 + p * 32 + k];
        }
#pragma unroll
        for (int a = 0; a < 5; ++a) pa[a] += __shfl_xor_sync(FULLM, pa[a], 1);
        if (p == 0) {
            float* hvp = g_hv + (size_t)(tile + slot) * 8;
            *(float4*)hvp = make_float4(pa[0], pa[1], pa[2], pa[3]);
            hvp[4] = pa[4];
        }
    }

    // GEMM per class from the same smem tile
    for (int cls = 0; cls < 3; ++cls) {
        if (slot < nN) {
            const float* wb = sW + cls * 4352 + p * 36;
            const float* er = sT + slot * 66;
            ull acc[16];
#pragma unroll
            for (int j = 0; j < 16; ++j) acc[j] = 0ull;
#pragma unroll 4
            for (int k2 = 0; k2 < 32; ++k2) {
                float2 e2 = *(const float2*)&er[2 * k2];
                ull b0 = dup_f(e2.x);
                ull b1 = dup_f(e2.y);
                const float* r0 = wb + (2 * k2) * 68;
                const float* r1 = r0 + 68;
#pragma unroll
                for (int j = 0; j < 8; ++j) {
                    ulonglong2 w0 = *(const ulonglong2*)(r0 + 4 * j);
                    FMA2(acc[2 * j],     w0.x, b0, acc[2 * j]);
                    FMA2(acc[2 * j + 1], w0.y, b0, acc[2 * j + 1]);
                }
#pragma unroll
                for (int j = 0; j < 8; ++j) {
                    ulonglong2 w1 = *(const ulonglong2*)(r1 + 4 * j);
                    FMA2(acc[2 * j],     w1.x, b1, acc[2 * j]);
                    FMA2(acc[2 * j + 1], w1.y, b1, acc[2 * j + 1]);
                }
            }
            float* ob = g_hW + ((size_t)cls * NN + tile + slot) * 64 + p * 32;
#pragma unroll
            for (int j = 0; j < 8; ++j) {
                float2 lo = *(float2*)&acc[2 * j];
                float2 hi = *(float2*)&acc[2 * j + 1];
                *(float4*)(ob + 4 * j) = make_float4(lo.x, lo.y, hi.x, hi.y);
            }
        }
    }
}

// ---------------- per-edge score ----------------
__global__ void score_kernel(const float* __restrict__ W2L, int isL0) {
    int e = blockIdx.x * blockDim.x + threadIdx.x;
    if (e >= NE) return;
    int4 m = __ldg(&g_eMeta[e]);
    int src = m.x & 0xFFFFF;
    const float4* rq4 = (const float4*)&g_rq[m.w * 8];
    float4 r0 = __ldg(&rq4[0]); float4 r1 = __ldg(&rq4[1]);
    float p0 = r0.x, p1 = r0.y, p2 = r0.z, p3 = r0.w, p4 = r1.x;
    if (!isL0) {
        const float4* hv4 = (const float4*)&g_hv[src * 8];
        float4 h0 = __ldg(&hv4[0]); float4 h1 = __ldg(&hv4[1]);
        p0 += h0.x; p1 += h0.y; p2 += h0.z; p3 += h0.w; p4 += h1.x;
    }
    float z = fmaxf(p0, 0.f) * __ldg(&W2L[0]) + fmaxf(p1, 0.f) * __ldg(&W2L[1])
            + fmaxf(p2, 0.f) * __ldg(&W2L[2]) + fmaxf(p3, 0.f) * __ldg(&W2L[3])
            + fmaxf(p4, 0.f) * __ldg(&W2L[4]);
    g_score[e] = 1.f / (1.f + __expf(-z));
}

// ---------------- main edge kernel (half-warp per edge, float4 lanes) ----------------
__global__ void __launch_bounds__(256) edge_kernel(int isL0) {
    int gw = (blockIdx.x * blockDim.x + threadIdx.x) >> 5;
    int lane = threadIdx.x & 31;
    int half = lane >> 4;
    int hl = lane & 15;
    int nw = (gridDim.x * blockDim.x) >> 5;
    for (int base = gw * 8; base < NE; base += nw * 8) {
#pragma unroll
        for (int p = 0; p < 4; ++p) {
            int e = base + 2 * p + half;
            int4 m = __ldg(&g_eMeta[e]);
            float s = __ldg(&g_score[e]);
            int src = m.x & 0xFFFFF;
            int cls = m.x >> 20;
            int rel = m.z & 511;
            int ta  = (m.z >> 9) & 511;
            float4 a = __ldg((const float4*)&g_RW[(cls * NRELP + rel) * 64 + 4 * hl]);
            float4 b = __ldg((const float4*)&g_TW[(cls * NTA + ta) * 64 + 4 * hl]);
            float vx = a.x + b.x, vy = a.y + b.y, vz = a.z + b.z, vw = a.w + b.w;
            if (!isL0) {
                float4 h = __ldg((const float4*)&g_hW[((size_t)cls * NN + src) * 64 + 4 * hl]);
                vx += h.x; vy += h.y; vz += h.z; vw += h.w;
            }
            red4(&g_next[(size_t)m.y * 64 + 4 * hl], s * vx, s * vy, s * vz, s * vw);
        }
    }
}

// ---------------- output: relu(g_next).Wc + bc ----------------
__global__ void out_kernel(const float* __restrict__ Wc, const float* __restrict__ bc,
                           const int* __restrict__ ob, const int* __restrict__ oe,
                           float* __restrict__ out) {
    int gw = (blockIdx.x * blockDim.x + threadIdx.x) >> 5;
    int lane = threadIdx.x & 31;
    if (gw >= NN) return;
    float2 h = *(const float2*)&g_next[(size_t)gw * 64 + 2 * lane];
    h.x = fmaxf(h.x, 0.f); h.y = fmaxf(h.y, 0.f);
    float2 w = __ldg((const float2*)&Wc[2 * lane]);
    float p = h.x * w.x + h.y * w.y;
#pragma unroll
    for (int off = 16; off; off >>= 1) p += __shfl_xor_sync(FULLM, p, off);
    if (lane == 0) out[ob[gw] * NENT + oe[gw]] = p + bc[0];
}

// ---------------- host launch ----------------
extern "C" void kernel_launch(void* const* d_in, const int* in_sizes, int n_in,
                              void* d_out, int out_size) {
    const int *bt, *si, *di, *ri, *rt, *qr, *ob, *oe;
    const float *rela, *te, *Wp, *Wn, *Wf, *W1, *W2, *Wc, *bc;

    if (in_sizes[0] == NE) {
        bt = (const int*)d_in[0];  si = (const int*)d_in[1];
        di = (const int*)d_in[2];  ri = (const int*)d_in[3];
        rt = (const int*)d_in[4];  qr = (const int*)d_in[5];
        ob = (const int*)d_in[6];  oe = (const int*)d_in[7];
        rela = (const float*)d_in[8];  te = (const float*)d_in[9];
        Wp = (const float*)d_in[10]; Wn = (const float*)d_in[11];
        Wf = (const float*)d_in[12]; W1 = (const float*)d_in[13];
        W2 = (const float*)d_in[14]; Wc = (const float*)d_in[15];
        bc = (const float*)d_in[16];
    } else {
        rela = (const float*)d_in[0];  te = (const float*)d_in[1];
        Wp = (const float*)d_in[2]; Wn = (const float*)d_in[3];
        Wf = (const float*)d_in[4]; W1 = (const float*)d_in[5];
        W2 = (const float*)d_in[6]; Wc = (const float*)d_in[7];
        bc = (const float*)d_in[8];
        bt = (const int*)d_in[9];  si = (const int*)d_in[10];
        di = (const int*)d_in[11]; ri = (const int*)d_in[12];
        rt = (const int*)d_in[13]; qr = (const int*)d_in[14];
        ob = (const int*)d_in[15]; oe = (const int*)d_in[16];
    }

    float* out = (float*)d_out;

    static int attr_done = 0;
    const int post_smem = (3 * 4352 + 128 * 66 + 5 * 64) * 4;   // 87296 B
    if (!attr_done) {
        cudaFuncSetAttribute(post_kernel, cudaFuncAttributeMaxDynamicSharedMemorySize, post_smem);
        attr_done = 1;
    }

    init_kernel<<<1600, 256>>>(out, out_size);

    // counting sort by src
    hist_kernel<<<(NE + 255) / 256, 256>>>(si);
    sum_chunk_kernel<<<NCHUNK, 256>>>();
    scan_part_kernel<<<1, 32>>>();
    off_kernel<<<NCHUNK, 256>>>();
    scatter_sort_kernel<<<(NE + 255) / 256, 256>>>(si, di, ri, rt, bt);

    for (int layer = 0; layer < NL; ++layer) {
        const float* relaL = rela + layer * NRELP * NH;
        const float* W1L = W1 + layer * 5 * 192;
        int isL0 = (layer == 0) ? 1 : 0;
        rwtw_kernel<<<(1788 * 32 + 255) / 256, 256>>>(relaL, te, Wp, Wn, Wf);
        rq_kernel<<<(NB * NRELP * 32 + 255) / 256, 256>>>(relaL, W1L, qr);
        score_kernel<<<(NE + 255) / 256, 256>>>(W2 + layer * 5, isL0);
        edge_kernel<<<1184, 256>>>(isL0);
        if (layer < NL - 1) {
            // hv/hW for the NEXT layer, from relu(g_next); zeros g_next
            post_kernel<<<(NN + 127) / 128, 256, post_smem>>>(
                Wp, Wn, Wf, W1 + (layer + 1) * 5 * 192);
        }
    }

    out_kernel<<<(NN * 32 + 255) / 256, 256>>>(Wc, bc, ob, oe, out);
}

// round 9
// speedup vs baseline: 1.1404x; 1.1404x over previous
#include <cuda_runtime.h>
#include <cuda_fp16.h>

#define NB 32
#define NN 100000
#define NE 1000000
#define NH 64
#define NL 3
#define NRELP 231
#define NTA 365
#define NENT 7128
#define FULLM 0xffffffffu
#define CH 1024
#define NCHUNK 98   // ceil(NN/CH)

typedef unsigned long long ull;

// ---------------- device scratch ----------------
static __device__ float   g_hidden[NN * NH];        // 25.6 MB
static __device__ float   g_next[NN * NH];          // 25.6 MB
static __device__ __half2 g_hWh[3 * NN * 32];       // 38.4 MB transformed hidden (fp16)
static __device__ float   g_RW[3 * NRELP * NH];     // rela @ W_cls^T
static __device__ float   g_TW[3 * NTA * NH];       // time @ W_cls^T (layer-invariant)
static __device__ int2    g_eMeta[NE];              // {src|cls<<17|ta<<19, dst|rel<<17|b<<25}
static __device__ float   g_score[NE];
static __device__ float   g_hv[NN * 8];
static __device__ float   g_rq[NB * NRELP * 8];
static __device__ int     g_hist[NN];
static __device__ int     g_off[NN];

#define FMA2(d, a, b, c) \
    asm("fma.rn.f32x2 %0, %1, %2, %3;" : "=l"(d) : "l"(a), "l"(b), "l"(c))

__device__ __forceinline__ ull dup_f(float x) {
    ull r; unsigned u = __float_as_uint(x);
    asm("mov.b64 %0, {%1, %1};" : "=l"(r) : "r"(u));
    return r;
}
__device__ __forceinline__ void red4(float* p, float x, float y, float z, float w) {
    asm volatile("red.global.add.v4.f32 [%0], {%1, %2, %3, %4};"
                 :: "l"(p), "f"(x), "f"(y), "f"(z), "f"(w) : "memory");
}

// ---------------- fused init: g_next, g_hist, out ----------------
__global__ void init_kernel(float* out, int n_out) {
    int i = blockIdx.x * blockDim.x + threadIdx.x;
    int stride = gridDim.x * blockDim.x;
    const int n4 = NN * NH / 4;
    for (int j = i; j < n4; j += stride)
        ((float4*)g_next)[j] = make_float4(0.f, 0.f, 0.f, 0.f);
    for (int j = i; j < NN; j += stride) g_hist[j] = 0;
    for (int j = i; j < n_out; j += stride) out[j] = 0.f;
}

// ---------------- counting sort by src ----------------
__global__ void hist_kernel(const int* __restrict__ src_idx) {
    int e = blockIdx.x * blockDim.x + threadIdx.x;
    if (e < NE) atomicAdd(&g_hist[src_idx[e]], 1);
}
// per-block redundant prefix over preceding chunks + in-chunk scan (no serial kernel)
__global__ void offscan_kernel() {
    __shared__ int sd[256];
    __shared__ int sbase;
    int b = blockIdx.x, t = threadIdx.x;
    int lim = b * CH;
    int s = 0;
    for (int i = t; i < lim; i += 256) s += g_hist[i];
    sd[t] = s; __syncthreads();
    for (int o = 128; o; o >>= 1) { if (t < o) sd[t] += sd[t + o]; __syncthreads(); }
    if (t == 0) sbase = sd[0];
    __syncthreads();
    int chunkbase = sbase;
    __syncthreads();
    int idx = b * CH + t * 4;
    int h0 = (idx + 0 < NN) ? g_hist[idx + 0] : 0;
    int h1 = (idx + 1 < NN) ? g_hist[idx + 1] : 0;
    int h2 = (idx + 2 < NN) ? g_hist[idx + 2] : 0;
    int h3 = (idx + 3 < NN) ? g_hist[idx + 3] : 0;
    int sum = h0 + h1 + h2 + h3;
    sd[t] = sum; __syncthreads();
    for (int o = 1; o < 256; o <<= 1) {
        int v = (t >= o) ? sd[t - o] : 0;
        __syncthreads();
        sd[t] += v;
        __syncthreads();
    }
    int base = chunkbase + sd[t] - sum;
    if (idx + 0 < NN) g_off[idx + 0] = base;
    if (idx + 1 < NN) g_off[idx + 1] = base + h0;
    if (idx + 2 < NN) g_off[idx + 2] = base + h0 + h1;
    if (idx + 3 < NN) g_off[idx + 3] = base + h0 + h1 + h2;
}
__global__ void scatter_sort_kernel(const int* __restrict__ src_idx,
                                    const int* __restrict__ dst_idx,
                                    const int* __restrict__ rel_idx,
                                    const int* __restrict__ rel_time,
                                    const int* __restrict__ batch_idx) {
    int e = blockIdx.x * blockDim.x + threadIdx.x;
    if (e >= NE) return;
    int src = src_idx[e];
    int rt  = rel_time[e];
    int cls = rt > 0 ? 2 : (rt == 0 ? 1 : 0);  // 0=past(Wp) 1=now(Wn) 2=future(Wf)
    int ta  = rt < 0 ? -rt : rt;
    int rel = rel_idx[e];
    int pos = atomicAdd(&g_off[src], 1);
    g_eMeta[pos] = make_int2(src | (cls << 17) | (ta << 19),
                             dst_idx[e] | (rel << 17) | (batch_idx[e] << 25));
}

// ---------------- per-layer tables ----------------
// RW rows (w < 693) always; TW rows (693 <= w < 1788) only when grid covers them (layer 0).
__global__ void rwtw_kernel(const float* __restrict__ relaL,
                            const float* __restrict__ timeE,
                            const float* __restrict__ Wp,
                            const float* __restrict__ Wn,
                            const float* __restrict__ Wf) {
    int w = (blockIdx.x * blockDim.x + threadIdx.x) >> 5;
    int lane = threadIdx.x & 31;
    const int NROW = 3 * NRELP + 3 * NTA;   // 1788
    if (w >= NROW) return;
    const float* in; float* out; int cls;
    if (w < 3 * NRELP) {
        cls = w / NRELP;
        in = relaL + (w % NRELP) * NH;
        out = g_RW + w * NH;
    } else {
        int w2 = w - 3 * NRELP;
        cls = w2 / NTA;
        in = timeE + (w2 % NTA) * NH;
        out = g_TW + w2 * NH;
    }
    const float* W = (cls == 0) ? Wp : ((cls == 1) ? Wn : Wf);
    float2 ev = __ldg((const float2*)&in[2 * lane]);
    int h0 = 2 * lane;
    float a0 = 0.f, a1 = 0.f;
#pragma unroll 8
    for (int k2 = 0; k2 < 32; ++k2) {
        float bx = __shfl_sync(FULLM, ev.x, k2);
        float by = __shfl_sync(FULLM, ev.y, k2);
        float2 w0 = __ldg((const float2*)&W[h0 * 64 + 2 * k2]);
        float2 w1 = __ldg((const float2*)&W[(h0 + 1) * 64 + 2 * k2]);
        a0 += bx * w0.x + by * w0.y;
        a1 += bx * w1.x + by * w1.y;
    }
    out[h0] = a0; out[h0 + 1] = a1;
}

// hv[n][a] = hidden[n] . W1[l][a][0:64]
__global__ void hv_kernel(const float* __restrict__ W1L) {
    int w = (blockIdx.x * blockDim.x + threadIdx.x) >> 5;
    int lane = threadIdx.x & 31;
    if (w >= NN) return;
    float2 h = *(const float2*)&g_hidden[w * 64 + 2 * lane];
    float p[5];
#pragma unroll
    for (int a = 0; a < 5; ++a) {
        float2 u = __ldg((const float2*)&W1L[a * 192 + 2 * lane]);
        p[a] = h.x * u.x + h.y * u.y;
    }
#pragma unroll
    for (int a = 0; a < 5; ++a)
#pragma unroll
        for (int off = 16; off; off >>= 1) p[a] += __shfl_xor_sync(FULLM, p[a], off);
    if (lane == 0) {
#pragma unroll
        for (int a = 0; a < 5; ++a) g_hv[w * 8 + a] = p[a];
    }
}

// rq[b*231+r][a] = rela[r].W1seg1_a + rela[qr_b].W1seg2_a
__global__ void rq_kernel(const float* __restrict__ relaL,
                          const float* __restrict__ W1L,
                          const int* __restrict__ query_rel) {
    int w = (blockIdx.x * blockDim.x + threadIdx.x) >> 5;
    int lane = threadIdx.x & 31;
    if (w >= NB * NRELP) return;
    int b = w / NRELP, r = w % NRELP;
    int qrb = __ldg(&query_rel[b]);
    float2 re = __ldg((const float2*)&relaL[r * 64 + 2 * lane]);
    float2 qe = __ldg((const float2*)&relaL[qrb * 64 + 2 * lane]);
    float p[5];
#pragma unroll
    for (int a = 0; a < 5; ++a) {
        float2 v  = __ldg((const float2*)&W1L[a * 192 + 64 + 2 * lane]);
        float2 ww = __ldg((const float2*)&W1L[a * 192 + 128 + 2 * lane]);
        p[a] = re.x * v.x + re.y * v.y + qe.x * ww.x + qe.y * ww.y;
    }
#pragma unroll
    for (int a = 0; a < 5; ++a)
#pragma unroll
        for (int off = 16; off; off >>= 1) p[a] += __shfl_xor_sync(FULLM, p[a], off);
    if (lane == 0) {
#pragma unroll
        for (int a = 0; a < 5; ++a) g_rq[w * 8 + a] = p[a];
    }
}

// hW[cls][node] = hidden[node] @ W_cls^T  -> fp16 (half2)
__global__ void __launch_bounds__(256) hw_kernel(const float* __restrict__ Wp,
                                                 const float* __restrict__ Wn,
                                                 const float* __restrict__ Wf) {
    extern __shared__ float dyn[];
    float* sW = dyn;            // 4352 floats
    float* sT = dyn + 4352;     // 128*66 floats
    int cls = blockIdx.y;
    const float* W = (cls == 0) ? Wp : ((cls == 1) ? Wn : Wf);
    int t = threadIdx.x;
    for (int idx = t; idx < 4096; idx += 256) {
        int h = idx >> 6, k = idx & 63;
        sW[k * 68 + h + (h >= 32 ? 4 : 0)] = __ldg(&W[h * 64 + k]);
    }
    __syncthreads();
    for (int tile = blockIdx.x * 128; tile < NN; tile += gridDim.x * 128) {
        int nN = min(128, NN - tile);
        for (int j = t; j < nN * 32; j += 256) {
            int nl = j >> 5, l = j & 31;
            *(float2*)&sT[nl * 66 + 2 * l] = *(const float2*)&g_hidden[(tile + nl) * 64 + 2 * l];
        }
        __syncthreads();
        int slot = t >> 1, p = t & 1;
        if (slot < nN) {
            const float* wb = sW + p * 36;
            const float* er = sT + slot * 66;
            ull acc[16];
#pragma unroll
            for (int j = 0; j < 16; ++j) acc[j] = 0ull;
#pragma unroll 4
            for (int k2 = 0; k2 < 32; ++k2) {
                float2 e2 = *(const float2*)&er[2 * k2];
                ull b0 = dup_f(e2.x);
                ull b1 = dup_f(e2.y);
                const float* r0 = wb + (2 * k2) * 68;
                const float* r1 = r0 + 68;
#pragma unroll
                for (int j = 0; j < 8; ++j) {
                    ulonglong2 w0 = *(const ulonglong2*)(r0 + 4 * j);
                    FMA2(acc[2 * j],     w0.x, b0, acc[2 * j]);
                    FMA2(acc[2 * j + 1], w0.y, b0, acc[2 * j + 1]);
                }
#pragma unroll
                for (int j = 0; j < 8; ++j) {
                    ulonglong2 w1 = *(const ulonglong2*)(r1 + 4 * j);
                    FMA2(acc[2 * j],     w1.x, b1, acc[2 * j]);
                    FMA2(acc[2 * j + 1], w1.y, b1, acc[2 * j + 1]);
                }
            }
            // convert 32 floats -> 16 half2, store 64B
            __half2 hh[16];
#pragma unroll
            for (int j = 0; j < 16; ++j) {
                float2 f = *(float2*)&acc[j];
                hh[j] = __float22half2_rn(f);
            }
            __half2* ob = g_hWh + ((size_t)cls * NN + tile + slot) * 32 + p * 16;
#pragma unroll
            for (int j = 0; j < 4; ++j)
                *(uint4*)(ob + 4 * j) = *(uint4*)(hh + 4 * j);
        }
        __syncthreads();
    }
}

// ---------------- per-edge score ----------------
__global__ void score_kernel(const float* __restrict__ W2L, int isL0) {
    int e = blockIdx.x * blockDim.x + threadIdx.x;
    if (e >= NE) return;
    int2 m = __ldg(&g_eMeta[e]);
    int src = m.x & 0x1FFFF;
    int rel = (m.y >> 17) & 0xFF;
    int b   = (m.y >> 25) & 0x1F;
    const float4* rq4 = (const float4*)&g_rq[(b * NRELP + rel) * 8];
    float4 r0 = __ldg(&rq4[0]); float4 r1 = __ldg(&rq4[1]);
    float p0 = r0.x, p1 = r0.y, p2 = r0.z, p3 = r0.w, p4 = r1.x;
    if (!isL0) {
        const float4* hv4 = (const float4*)&g_hv[src * 8];
        float4 h0 = __ldg(&hv4[0]); float4 h1 = __ldg(&hv4[1]);
        p0 += h0.x; p1 += h0.y; p2 += h0.z; p3 += h0.w; p4 += h1.x;
    }
    float z = fmaxf(p0, 0.f) * __ldg(&W2L[0]) + fmaxf(p1, 0.f) * __ldg(&W2L[1])
            + fmaxf(p2, 0.f) * __ldg(&W2L[2]) + fmaxf(p3, 0.f) * __ldg(&W2L[3])
            + fmaxf(p4, 0.f) * __ldg(&W2L[4]);
    g_score[e] = 1.f / (1.f + __expf(-z));
}

// ---------------- main edge kernel (half-warp per edge, float4 lanes) ----------------
__global__ void __launch_bounds__(256) edge_kernel(int isL0) {
    int gw = (blockIdx.x * blockDim.x + threadIdx.x) >> 5;
    int lane = threadIdx.x & 31;
    int half = lane >> 4;
    int hl = lane & 15;
    int nw = (gridDim.x * blockDim.x) >> 5;
    for (int base = gw * 8; base < NE; base += nw * 8) {
#pragma unroll
        for (int p = 0; p < 4; ++p) {
            int e = base + 2 * p + half;
            int2 m = __ldg(&g_eMeta[e]);
            float s = __ldg(&g_score[e]);
            int src = m.x & 0x1FFFF;
            int cls = (m.x >> 17) & 3;
            int ta  = (m.x >> 19) & 0x1FF;
            int dst = m.y & 0x1FFFF;
            int rel = (m.y >> 17) & 0xFF;
            float4 a = __ldg((const float4*)&g_RW[(cls * NRELP + rel) * 64 + 4 * hl]);
            float4 b = __ldg((const float4*)&g_TW[(cls * NTA + ta) * 64 + 4 * hl]);
            float vx = a.x + b.x, vy = a.y + b.y, vz = a.z + b.z, vw = a.w + b.w;
            if (!isL0) {
                uint2 raw = __ldg((const uint2*)(g_hWh + ((size_t)cls * NN + src) * 32 + 2 * hl));
                float2 h01 = __half22float2(*(__half2*)&raw.x);
                float2 h23 = __half22float2(*(__half2*)&raw.y);
                vx += h01.x; vy += h01.y; vz += h23.x; vw += h23.y;
            }
            red4(&g_next[(size_t)dst * 64 + 4 * hl], s * vx, s * vy, s * vz, s * vw);
        }
    }
}

// ---------------- hidden = relu(next); next = 0 ----------------
__global__ void relu_reset_kernel() {
    int i = blockIdx.x * blockDim.x + threadIdx.x;
    const int n4 = NN * NH / 4;
    if (i < n4) {
        float4 v = ((float4*)g_next)[i];
        v.x = fmaxf(v.x, 0.f); v.y = fmaxf(v.y, 0.f);
        v.z = fmaxf(v.z, 0.f); v.w = fmaxf(v.w, 0.f);
        ((float4*)g_hidden)[i] = v;
        ((float4*)g_next)[i] = make_float4(0.f, 0.f, 0.f, 0.f);
    }
}

// ---------------- output ----------------
__global__ void out_kernel(const float* __restrict__ Wc, const float* __restrict__ bc,
                           const int* __restrict__ ob, const int* __restrict__ oe,
                           float* __restrict__ out) {
    int gw = (blockIdx.x * blockDim.x + threadIdx.x) >> 5;
    int lane = threadIdx.x & 31;
    if (gw >= NN) return;
    float2 h = *(const float2*)&g_hidden[gw * 64 + 2 * lane];
    float2 w = __ldg((const float2*)&Wc[2 * lane]);
    float p = h.x * w.x + h.y * w.y;
#pragma unroll
    for (int off = 16; off; off >>= 1) p += __shfl_xor_sync(FULLM, p, off);
    if (lane == 0) out[ob[gw] * NENT + oe[gw]] = p + bc[0];
}

// ---------------- host launch ----------------
extern "C" void kernel_launch(void* const* d_in, const int* in_sizes, int n_in,
                              void* d_out, int out_size) {
    const int *bt, *si, *di, *ri, *rt, *qr, *ob, *oe;
    const float *rela, *te, *Wp, *Wn, *Wf, *W1, *W2, *Wc, *bc;

    if (in_sizes[0] == NE) {
        bt = (const int*)d_in[0];  si = (const int*)d_in[1];
        di = (const int*)d_in[2];  ri = (const int*)d_in[3];
        rt = (const int*)d_in[4];  qr = (const int*)d_in[5];
        ob = (const int*)d_in[6];  oe = (const int*)d_in[7];
        rela = (const float*)d_in[8];  te = (const float*)d_in[9];
        Wp = (const float*)d_in[10]; Wn = (const float*)d_in[11];
        Wf = (const float*)d_in[12]; W1 = (const float*)d_in[13];
        W2 = (const float*)d_in[14]; Wc = (const float*)d_in[15];
        bc = (const float*)d_in[16];
    } else {
        rela = (const float*)d_in[0];  te = (const float*)d_in[1];
        Wp = (const float*)d_in[2]; Wn = (const float*)d_in[3];
        Wf = (const float*)d_in[4]; W1 = (const float*)d_in[5];
        W2 = (const float*)d_in[6]; Wc = (const float*)d_in[7];
        bc = (const float*)d_in[8];
        bt = (const int*)d_in[9];  si = (const int*)d_in[10];
        di = (const int*)d_in[11]; ri = (const int*)d_in[12];
        rt = (const int*)d_in[13]; qr = (const int*)d_in[14];
        ob = (const int*)d_in[15]; oe = (const int*)d_in[16];
    }

    float* out = (float*)d_out;

    static int attr_done = 0;
    const int hw_smem = (4352 + 128 * 66) * 4;   // 51200 B
    if (!attr_done) {
        cudaFuncSetAttribute(hw_kernel, cudaFuncAttributeMaxDynamicSharedMemorySize, hw_smem);
        attr_done = 1;
    }

    const int n4 = NN * NH / 4;

    init_kernel<<<1600, 256>>>(out, out_size);

    // counting sort by src
    hist_kernel<<<(NE + 255) / 256, 256>>>(si);
    offscan_kernel<<<NCHUNK, 256>>>();
    scatter_sort_kernel<<<(NE + 255) / 256, 256>>>(si, di, ri, rt, bt);

    for (int layer = 0; layer < NL; ++layer) {
        const float* relaL = rela + layer * NRELP * NH;
        const float* W1L = W1 + layer * 5 * 192;
        int isL0 = (layer == 0) ? 1 : 0;
        // layer 0 computes both RW and TW; later layers only RW (TW layer-invariant)
        int tblrows = isL0 ? 1788 : 693;
        rwtw_kernel<<<(tblrows * 32 + 255) / 256, 256>>>(relaL, te, Wp, Wn, Wf);
        rq_kernel<<<(NB * NRELP * 32 + 255) / 256, 256>>>(relaL, W1L, qr);
        if (!isL0) {
            hv_kernel<<<(NN * 32 + 255) / 256, 256>>>(W1L);
            hw_kernel<<<dim3((NN + 127) / 128, 3), 256, hw_smem>>>(Wp, Wn, Wf);
        }
        score_kernel<<<(NE + 255) / 256, 256>>>(W2 + layer * 5, isL0);
        edge_kernel<<<1184, 256>>>(isL0);
        relu_reset_kernel<<<(n4 + 255) / 256, 256>>>();
    }

    out_kernel<<<(NN * 32 + 255) / 256, 256>>>(Wc, bc, ob, oe, out);
}

// round 10
// speedup vs baseline: 1.2400x; 1.0873x over previous
#include <cuda_runtime.h>
#include <cuda_fp16.h>

#define NB 32
#define NN 100000
#define NE 1000000
#define NH 64
#define NL 3
#define NRELP 231
#define NTA 365
#define NENT 7128
#define FULLM 0xffffffffu
#define CH 1024
#define NCHUNK 98   // ceil(NN/CH)

typedef unsigned long long ull;

// ---------------- device scratch ----------------
static __device__ float   g_hidden[NN * NH];        // 25.6 MB
static __device__ float   g_next[NN * NH];          // 25.6 MB
static __device__ __half2 g_hWh[3 * NN * 32];       // 38.4 MB transformed hidden (fp16)
static __device__ __half2 g_RWh[3 * NRELP * 32];    // rela @ W_cls^T (fp16)
static __device__ __half2 g_TWh[3 * NTA * 32];      // time @ W_cls^T (fp16, layer-invariant)
static __device__ int2    g_eMeta[NE];              // {src|cls<<17|ta<<19, dst|rel<<17|b<<25}
static __device__ float   g_score[NE];
static __device__ float   g_hv[NN * 8];
static __device__ float   g_rq[NB * NRELP * 8];
static __device__ int     g_hist[NN];
static __device__ int     g_off[NN];

#define FMA2(d, a, b, c) \
    asm("fma.rn.f32x2 %0, %1, %2, %3;" : "=l"(d) : "l"(a), "l"(b), "l"(c))

__device__ __forceinline__ ull dup_f(float x) {
    ull r; unsigned u = __float_as_uint(x);
    asm("mov.b64 %0, {%1, %1};" : "=l"(r) : "r"(u));
    return r;
}
__device__ __forceinline__ void red4(float* p, float x, float y, float z, float w) {
    asm volatile("red.global.add.v4.f32 [%0], {%1, %2, %3, %4};"
                 :: "l"(p), "f"(x), "f"(y), "f"(z), "f"(w) : "memory");
}

// ---------------- fused init: g_next, g_hist, out ----------------
__global__ void init_kernel(float* out, int n_out) {
    int i = blockIdx.x * blockDim.x + threadIdx.x;
    int stride = gridDim.x * blockDim.x;
    const int n4 = NN * NH / 4;
    for (int j = i; j < n4; j += stride)
        ((float4*)g_next)[j] = make_float4(0.f, 0.f, 0.f, 0.f);
    for (int j = i; j < NN; j += stride) g_hist[j] = 0;
    for (int j = i; j < n_out; j += stride) out[j] = 0.f;
}

// ---------------- counting sort by src ----------------
__global__ void hist_kernel(const int* __restrict__ src_idx) {
    int e = blockIdx.x * blockDim.x + threadIdx.x;
    if (e < NE) atomicAdd(&g_hist[src_idx[e]], 1);
}
__global__ void offscan_kernel() {
    __shared__ int sd[256];
    __shared__ int sbase;
    int b = blockIdx.x, t = threadIdx.x;
    int lim = b * CH;
    int s = 0;
    for (int i = t; i < lim; i += 256) s += g_hist[i];
    sd[t] = s; __syncthreads();
    for (int o = 128; o; o >>= 1) { if (t < o) sd[t] += sd[t + o]; __syncthreads(); }
    if (t == 0) sbase = sd[0];
    __syncthreads();
    int chunkbase = sbase;
    __syncthreads();
    int idx = b * CH + t * 4;
    int h0 = (idx + 0 < NN) ? g_hist[idx + 0] : 0;
    int h1 = (idx + 1 < NN) ? g_hist[idx + 1] : 0;
    int h2 = (idx + 2 < NN) ? g_hist[idx + 2] : 0;
    int h3 = (idx + 3 < NN) ? g_hist[idx + 3] : 0;
    int sum = h0 + h1 + h2 + h3;
    sd[t] = sum; __syncthreads();
    for (int o = 1; o < 256; o <<= 1) {
        int v = (t >= o) ? sd[t - o] : 0;
        __syncthreads();
        sd[t] += v;
        __syncthreads();
    }
    int base = chunkbase + sd[t] - sum;
    if (idx + 0 < NN) g_off[idx + 0] = base;
    if (idx + 1 < NN) g_off[idx + 1] = base + h0;
    if (idx + 2 < NN) g_off[idx + 2] = base + h0 + h1;
    if (idx + 3 < NN) g_off[idx + 3] = base + h0 + h1 + h2;
}
__global__ void scatter_sort_kernel(const int* __restrict__ src_idx,
                                    const int* __restrict__ dst_idx,
                                    const int* __restrict__ rel_idx,
                                    const int* __restrict__ rel_time,
                                    const int* __restrict__ batch_idx) {
    int e = blockIdx.x * blockDim.x + threadIdx.x;
    if (e >= NE) return;
    int src = src_idx[e];
    int rt  = rel_time[e];
    int cls = rt > 0 ? 2 : (rt == 0 ? 1 : 0);  // 0=past(Wp) 1=now(Wn) 2=future(Wf)
    int ta  = rt < 0 ? -rt : rt;
    int rel = rel_idx[e];
    int pos = atomicAdd(&g_off[src], 1);
    g_eMeta[pos] = make_int2(src | (cls << 17) | (ta << 19),
                             dst_idx[e] | (rel << 17) | (batch_idx[e] << 25));
}

// ---------------- per-layer tables (fp16 out) ----------------
__global__ void rwtw_kernel(const float* __restrict__ relaL,
                            const float* __restrict__ timeE,
                            const float* __restrict__ Wp,
                            const float* __restrict__ Wn,
                            const float* __restrict__ Wf) {
    int w = (blockIdx.x * blockDim.x + threadIdx.x) >> 5;
    int lane = threadIdx.x & 31;
    const int NROW = 3 * NRELP + 3 * NTA;   // 1788
    if (w >= NROW) return;
    const float* in; __half2* out; int cls;
    if (w < 3 * NRELP) {
        cls = w / NRELP;
        in = relaL + (w % NRELP) * NH;
        out = g_RWh + w * 32;
    } else {
        int w2 = w - 3 * NRELP;
        cls = w2 / NTA;
        in = timeE + (w2 % NTA) * NH;
        out = g_TWh + w2 * 32;
    }
    const float* W = (cls == 0) ? Wp : ((cls == 1) ? Wn : Wf);
    float2 ev = __ldg((const float2*)&in[2 * lane]);
    int h0 = 2 * lane;
    float a0 = 0.f, a1 = 0.f;
#pragma unroll 8
    for (int k2 = 0; k2 < 32; ++k2) {
        float bx = __shfl_sync(FULLM, ev.x, k2);
        float by = __shfl_sync(FULLM, ev.y, k2);
        float2 w0 = __ldg((const float2*)&W[h0 * 64 + 2 * k2]);
        float2 w1 = __ldg((const float2*)&W[(h0 + 1) * 64 + 2 * k2]);
        a0 += bx * w0.x + by * w0.y;
        a1 += bx * w1.x + by * w1.y;
    }
    out[lane] = __floats2half2_rn(a0, a1);
}

// rq[b*231+r][a] = rela[r].W1seg1_a + rela[qr_b].W1seg2_a
__global__ void rq_kernel(const float* __restrict__ relaL,
                          const float* __restrict__ W1L,
                          const int* __restrict__ query_rel) {
    int w = (blockIdx.x * blockDim.x + threadIdx.x) >> 5;
    int lane = threadIdx.x & 31;
    if (w >= NB * NRELP) return;
    int b = w / NRELP, r = w % NRELP;
    int qrb = __ldg(&query_rel[b]);
    float2 re = __ldg((const float2*)&relaL[r * 64 + 2 * lane]);
    float2 qe = __ldg((const float2*)&relaL[qrb * 64 + 2 * lane]);
    float p[5];
#pragma unroll
    for (int a = 0; a < 5; ++a) {
        float2 v  = __ldg((const float2*)&W1L[a * 192 + 64 + 2 * lane]);
        float2 ww = __ldg((const float2*)&W1L[a * 192 + 128 + 2 * lane]);
        p[a] = re.x * v.x + re.y * v.y + qe.x * ww.x + qe.y * ww.y;
    }
#pragma unroll
    for (int a = 0; a < 5; ++a)
#pragma unroll
        for (int off = 16; off; off >>= 1) p[a] += __shfl_xor_sync(FULLM, p[a], off);
    if (lane == 0) {
#pragma unroll
        for (int a = 0; a < 5; ++a) g_rq[w * 8 + a] = p[a];
    }
}

// hW[cls][node] = hidden[node] @ W_cls^T -> fp16; cls==0 blocks also emit hv
__global__ void __launch_bounds__(256) hw_kernel(const float* __restrict__ Wp,
                                                 const float* __restrict__ Wn,
                                                 const float* __restrict__ Wf,
                                                 const float* __restrict__ W1L) {
    extern __shared__ float dyn[];
    float* sW = dyn;            // 4352 floats
    float* sT = dyn + 4352;     // 128*66 floats
    float* sU = dyn + 4352 + 128 * 66;  // 5*64 floats
    int cls = blockIdx.y;
    const float* W = (cls == 0) ? Wp : ((cls == 1) ? Wn : Wf);
    int t = threadIdx.x;
    for (int idx = t; idx < 4096; idx += 256) {
        int h = idx >> 6, k = idx & 63;
        sW[k * 68 + h + (h >= 32 ? 4 : 0)] = __ldg(&W[h * 64 + k]);
    }
    if (cls == 0) {
        for (int idx = t; idx < 5 * 64; idx += 256) {
            int a = idx >> 6, k = idx & 63;
            sU[idx] = __ldg(&W1L[a * 192 + k]);
        }
    }
    __syncthreads();
    for (int tile = blockIdx.x * 128; tile < NN; tile += gridDim.x * 128) {
        int nN = min(128, NN - tile);
        for (int j = t; j < nN * 32; j += 256) {
            int nl = j >> 5, l = j & 31;
            *(float2*)&sT[nl * 66 + 2 * l] = *(const float2*)&g_hidden[(tile + nl) * 64 + 2 * l];
        }
        __syncthreads();
        int slot = t >> 1, p = t & 1;
        if (slot < nN) {
            // hv (cls 0 only): pair half-dots + shfl combine
            if (cls == 0) {
                const float* row = sT + slot * 66 + p * 32;
                float pa[5] = {0.f, 0.f, 0.f, 0.f, 0.f};
#pragma unroll 8
                for (int k = 0; k < 32; ++k) {
                    float hk = row[k];
#pragma unroll
                    for (int a = 0; a < 5; ++a) pa[a] += hk * sU[a * 64 + p * 32 + k];
                }
#pragma unroll
                for (int a = 0; a < 5; ++a) pa[a] += __shfl_xor_sync(FULLM, pa[a], 1);
                if (p == 0) {
                    float* hvp = g_hv + (size_t)(tile + slot) * 8;
                    *(float4*)hvp = make_float4(pa[0], pa[1], pa[2], pa[3]);
                    hvp[4] = pa[4];
                }
            }
            const float* wb = sW + p * 36;
            const float* er = sT + slot * 66;
            ull acc[16];
#pragma unroll
            for (int j = 0; j < 16; ++j) acc[j] = 0ull;
#pragma unroll 4
            for (int k2 = 0; k2 < 32; ++k2) {
                float2 e2 = *(const float2*)&er[2 * k2];
                ull b0 = dup_f(e2.x);
                ull b1 = dup_f(e2.y);
                const float* r0 = wb + (2 * k2) * 68;
                const float* r1 = r0 + 68;
#pragma unroll
                for (int j = 0; j < 8; ++j) {
                    ulonglong2 w0 = *(const ulonglong2*)(r0 + 4 * j);
                    FMA2(acc[2 * j],     w0.x, b0, acc[2 * j]);
                    FMA2(acc[2 * j + 1], w0.y, b0, acc[2 * j + 1]);
                }
#pragma unroll
                for (int j = 0; j < 8; ++j) {
                    ulonglong2 w1 = *(const ulonglong2*)(r1 + 4 * j);
                    FMA2(acc[2 * j],     w1.x, b1, acc[2 * j]);
                    FMA2(acc[2 * j + 1], w1.y, b1, acc[2 * j + 1]);
                }
            }
            __half2 hh[16];
#pragma unroll
            for (int j = 0; j < 16; ++j) {
                float2 f = *(float2*)&acc[j];
                hh[j] = __float22half2_rn(f);
            }
            __half2* ob = g_hWh + ((size_t)cls * NN + tile + slot) * 32 + p * 16;
#pragma unroll
            for (int j = 0; j < 4; ++j)
                *(uint4*)(ob + 4 * j) = *(uint4*)(hh + 4 * j);
        }
        __syncthreads();
    }
}

// ---------------- per-edge score ----------------
__global__ void score_kernel(const float* __restrict__ W2L, int isL0) {
    int e = blockIdx.x * blockDim.x + threadIdx.x;
    if (e >= NE) return;
    int2 m = __ldg(&g_eMeta[e]);
    int src = m.x & 0x1FFFF;
    int rel = (m.y >> 17) & 0xFF;
    int b   = (m.y >> 25) & 0x1F;
    const float4* rq4 = (const float4*)&g_rq[(b * NRELP + rel) * 8];
    float4 r0 = __ldg(&rq4[0]); float4 r1 = __ldg(&rq4[1]);
    float p0 = r0.x, p1 = r0.y, p2 = r0.z, p3 = r0.w, p4 = r1.x;
    if (!isL0) {
        const float4* hv4 = (const float4*)&g_hv[src * 8];
        float4 h0 = __ldg(&hv4[0]); float4 h1 = __ldg(&hv4[1]);
        p0 += h0.x; p1 += h0.y; p2 += h0.z; p3 += h0.w; p4 += h1.x;
    }
    float z = fmaxf(p0, 0.f) * __ldg(&W2L[0]) + fmaxf(p1, 0.f) * __ldg(&W2L[1])
            + fmaxf(p2, 0.f) * __ldg(&W2L[2]) + fmaxf(p3, 0.f) * __ldg(&W2L[3])
            + fmaxf(p4, 0.f) * __ldg(&W2L[4]);
    g_score[e] = 1.f / (1.f + __expf(-z));
}

// ---------------- main edge kernel (half-warp per edge, fp16 tables) ----------------
__global__ void __launch_bounds__(256) edge_kernel(int isL0) {
    int gw = (blockIdx.x * blockDim.x + threadIdx.x) >> 5;
    int lane = threadIdx.x & 31;
    int half = lane >> 4;
    int hl = lane & 15;
    int nw = (gridDim.x * blockDim.x) >> 5;
    for (int base = gw * 8; base < NE; base += nw * 8) {
#pragma unroll
        for (int p = 0; p < 4; ++p) {
            int e = base + 2 * p + half;
            int2 m = __ldg(&g_eMeta[e]);
            float s = __ldg(&g_score[e]);
            int src = m.x & 0x1FFFF;
            int cls = (m.x >> 17) & 3;
            int ta  = (m.x >> 19) & 0x1FF;
            int dst = m.y & 0x1FFFF;
            int rel = (m.y >> 17) & 0xFF;
            uint2 ra = __ldg((const uint2*)(g_RWh + (cls * NRELP + rel) * 32 + 2 * hl));
            uint2 tb = __ldg((const uint2*)(g_TWh + (cls * NTA + ta) * 32 + 2 * hl));
            __half2 t0 = __hadd2(*(__half2*)&ra.x, *(__half2*)&tb.x);
            __half2 t1 = __hadd2(*(__half2*)&ra.y, *(__half2*)&tb.y);
            if (!isL0) {
                uint2 hw = __ldg((const uint2*)(g_hWh + ((size_t)cls * NN + src) * 32 + 2 * hl));
                t0 = __hadd2(t0, *(__half2*)&hw.x);
                t1 = __hadd2(t1, *(__half2*)&hw.y);
            }
            float2 f01 = __half22float2(t0);
            float2 f23 = __half22float2(t1);
            red4(&g_next[(size_t)dst * 64 + 4 * hl], s * f01.x, s * f01.y, s * f23.x, s * f23.y);
        }
    }
}

// ---------------- hidden = relu(next); next = 0 ----------------
__global__ void relu_reset_kernel() {
    int i = blockIdx.x * blockDim.x + threadIdx.x;
    const int n4 = NN * NH / 4;
    if (i < n4) {
        float4 v = ((float4*)g_next)[i];
        v.x = fmaxf(v.x, 0.f); v.y = fmaxf(v.y, 0.f);
        v.z = fmaxf(v.z, 0.f); v.w = fmaxf(v.w, 0.f);
        ((float4*)g_hidden)[i] = v;
        ((float4*)g_next)[i] = make_float4(0.f, 0.f, 0.f, 0.f);
    }
}

// ---------------- output: relu(g_next).Wc + bc ----------------
__global__ void out_kernel(const float* __restrict__ Wc, const float* __restrict__ bc,
                           const int* __restrict__ ob, const int* __restrict__ oe,
                           float* __restrict__ out) {
    int gw = (blockIdx.x * blockDim.x + threadIdx.x) >> 5;
    int lane = threadIdx.x & 31;
    if (gw >= NN) return;
    float2 h = *(const float2*)&g_next[(size_t)gw * 64 + 2 * lane];
    h.x = fmaxf(h.x, 0.f); h.y = fmaxf(h.y, 0.f);
    float2 w = __ldg((const float2*)&Wc[2 * lane]);
    float p = h.x * w.x + h.y * w.y;
#pragma unroll
    for (int off = 16; off; off >>= 1) p += __shfl_xor_sync(FULLM, p, off);
    if (lane == 0) out[ob[gw] * NENT + oe[gw]] = p + bc[0];
}

// ---------------- host launch ----------------
extern "C" void kernel_launch(void* const* d_in, const int* in_sizes, int n_in,
                              void* d_out, int out_size) {
    const int *bt, *si, *di, *ri, *rt, *qr, *ob, *oe;
    const float *rela, *te, *Wp, *Wn, *Wf, *W1, *W2, *Wc, *bc;

    if (in_sizes[0] == NE) {
        bt = (const int*)d_in[0];  si = (const int*)d_in[1];
        di = (const int*)d_in[2];  ri = (const int*)d_in[3];
        rt = (const int*)d_in[4];  qr = (const int*)d_in[5];
        ob = (const int*)d_in[6];  oe = (const int*)d_in[7];
        rela = (const float*)d_in[8];  te = (const float*)d_in[9];
        Wp = (const float*)d_in[10]; Wn = (const float*)d_in[11];
        Wf = (const float*)d_in[12]; W1 = (const float*)d_in[13];
        W2 = (const float*)d_in[14]; Wc = (const float*)d_in[15];
        bc = (const float*)d_in[16];
    } else {
        rela = (const float*)d_in[0];  te = (const float*)d_in[1];
        Wp = (const float*)d_in[2]; Wn = (const float*)d_in[3];
        Wf = (const float*)d_in[4]; W1 = (const float*)d_in[5];
        W2 = (const float*)d_in[6]; Wc = (const float*)d_in[7];
        bc = (const float*)d_in[8];
        bt = (const int*)d_in[9];  si = (const int*)d_in[10];
        di = (const int*)d_in[11]; ri = (const int*)d_in[12];
        rt = (const int*)d_in[13]; qr = (const int*)d_in[14];
        ob = (const int*)d_in[15]; oe = (const int*)d_in[16];
    }

    float* out = (float*)d_out;

    static int attr_done = 0;
    const int hw_smem = (4352 + 128 * 66 + 5 * 64) * 4;   // 52480 B
    if (!attr_done) {
        cudaFuncSetAttribute(hw_kernel, cudaFuncAttributeMaxDynamicSharedMemorySize, hw_smem);
        attr_done = 1;
    }

    const int n4 = NN * NH / 4;

    init_kernel<<<1600, 256>>>(out, out_size);

    // counting sort by src
    hist_kernel<<<(NE + 255) / 256, 256>>>(si);
    offscan_kernel<<<NCHUNK, 256>>>();
    scatter_sort_kernel<<<(NE + 255) / 256, 256>>>(si, di, ri, rt, bt);

    for (int layer = 0; layer < NL; ++layer) {
        const float* relaL = rela + layer * NRELP * NH;
        const float* W1L = W1 + layer * 5 * 192;
        int isL0 = (layer == 0) ? 1 : 0;
        int tblrows = isL0 ? 1788 : 693;   // TW layer-invariant
        rwtw_kernel<<<(tblrows * 32 + 255) / 256, 256>>>(relaL, te, Wp, Wn, Wf);
        rq_kernel<<<(NB * NRELP * 32 + 255) / 256, 256>>>(relaL, W1L, qr);
        if (!isL0) {
            // hv fused into hw_kernel (cls==0 blocks)
            hw_kernel<<<dim3((NN + 127) / 128, 3), 256, hw_smem>>>(Wp, Wn, Wf, W1L);
        }
        score_kernel<<<(NE + 255) / 256, 256>>>(W2 + layer * 5, isL0);
        edge_kernel<<<1184, 256>>>(isL0);
        if (layer < NL - 1)
            relu_reset_kernel<<<(n4 + 255) / 256, 256>>>();
    }

    out_kernel<<<(NN * 32 + 255) / 256, 256>>>(Wc, bc, ob, oe, out);
}